// round 2
// baseline (speedup 1.0000x reference)
#include <cuda_runtime.h>

#define AA 5
#define THREADS 256
#define ROWS_PB 160            // rows (of the 655360 flattened proj rows) per block
#define GROUPS_PB 32           // attention groups per block
#define NBLOCKS 4096           // 655360 / 160

// Fused weights (computed by prep_kernel every launch)
__device__ float g_Wqk[AA][96][32];   // rows j<48: q (j=h*24+d), j in [48,96): k
__device__ float g_bqk[AA][96];
__device__ float g_Wvo[AA][96][32];   // row r = h*48+e : fused v@out_w
__device__ float g_bvo[AA][96];

__global__ void prep_kernel(const float* __restrict__ agg_W,
                            const float* __restrict__ agg_b,
                            const float* __restrict__ ipw,
                            const float* __restrict__ ipb,
                            const float* __restrict__ out_w)
{
    int bid = blockIdx.x;
    if (bid < AA) {
        int a = bid;
        for (int o = threadIdx.x; o < 96*32; o += THREADS) {
            int j = o >> 5, c = o & 31;
            float acc = 0.f;
            for (int e = 0; e < 48; e++)
                acc += ipw[j*48+e] * agg_W[(a*48+e)*32 + c];
            g_Wqk[a][j][c] = acc;
        }
        for (int j = threadIdx.x; j < 96; j += THREADS) {
            float acc = ipb[j];
            for (int e = 0; e < 48; e++)
                acc += ipw[j*48+e] * agg_b[a*48+e];
            g_bqk[a][j] = acc;
        }
    } else {
        int a = (bid - AA) >> 1;
        int h = (bid - AA) & 1;
        __shared__ float Wv[24][32];
        __shared__ float bv[24];
        for (int o = threadIdx.x; o < 24*32; o += THREADS) {
            int d = o >> 5, c = o & 31;
            int row = 96 + h*24 + d;
            float acc = 0.f;
            for (int e = 0; e < 48; e++)
                acc += ipw[row*48+e] * agg_W[(a*48+e)*32 + c];
            Wv[d][c] = acc;
        }
        for (int d = threadIdx.x; d < 24; d += THREADS) {
            int row = 96 + h*24 + d;
            float acc = ipb[row];
            for (int e = 0; e < 48; e++)
                acc += ipw[row*48+e] * agg_b[a*48+e];
            bv[d] = acc;
        }
        __syncthreads();
        for (int o = threadIdx.x; o < 48*32; o += THREADS) {
            int e = o >> 5, c = o & 31;
            float acc = 0.f;
            for (int d = 0; d < 24; d++)
                acc += Wv[d][c] * out_w[e*48 + h*24 + d];
            g_Wvo[a][h*48 + e][c] = acc;
        }
        for (int e = threadIdx.x; e < 48; e += THREADS) {
            float acc = 0.f;
            for (int d = 0; d < 24; d++)
                acc += bv[d] * out_w[e*48 + h*24 + d];
            g_bvo[a][h*48 + e] = acc;
        }
    }
}

// Shared layout (floats):
//   qkbuf : 160*96  (q/k per local row, then reused for vo)
//   pbuf  : 32*50   (softmax probs [g][h*5+i][j])
//   wA,wB : 96*33 each (staged weights; stage-5 reuses this region as 48*97)
#define SM_P      (ROWS_PB*96)
#define SM_WA     (SM_P + GROUPS_PB*50)
#define SM_WB     (SM_WA + 96*33)
#define SM_FLOATS (SM_WB + 96*33)

// x offset of the 32-float agg slice feeding flattened proj row r
__device__ __forceinline__ long row_xoff(int r)
{
    int a  = (r >> 12) % 5;                 // (r/4096) % 5
    int tx = (r / 20480) * 4096 + (r & 4095);
    return (long)tx * 256 + a * 32;
}

__global__ void __launch_bounds__(THREADS, 2)
main_kernel(const float* __restrict__ x,
            const float* __restrict__ extra_w,
            const float* __restrict__ extra_b,
            const float* __restrict__ out_b,
            float* __restrict__ out)
{
    extern __shared__ float sm[];
    float* qkbuf = sm;
    float* pbuf  = sm + SM_P;
    float* wA    = sm + SM_WA;
    float* wB    = sm + SM_WB;

    const int tid = threadIdx.x;
    const int z   = tid & 15;
    const int t0  = tid >> 4;
    const int r0  = blockIdx.x * ROWS_PB;
    const int m0  = blockIdx.x * GROUPS_PB;

    const int  blk4k = r0 >> 12;
    const int  a_lo  = blk4k % 5;
    const int  Bnd   = (blk4k + 1) << 12;        // first row with the next 'a'
    const bool has_b = (r0 + ROWS_PB) > Bnd;     // boundary falls inside this block
    const int  a_hi  = has_b ? ((a_lo + 1) % 5) : a_lo;

    // ================= stage 1: qk = x_slice @ Wqk[a]^T + bqk ==============
    for (int i = tid; i < 96*32; i += THREADS) {
        int j = i >> 5, c = i & 31;
        wA[j*33 + c] = g_Wqk[a_lo][j][c];
        if (has_b) wB[j*33 + c] = g_Wqk[a_hi][j][c];
    }
    __syncthreads();

    for (int ch = 0; ch < 5; ch++) {
        const int lr0 = ch*32 + t0;
        const int lr1 = lr0 + 16;
        const int rg0 = r0 + lr0, rg1 = r0 + lr1;
        const float* xp0 = x + row_xoff(rg0);
        const float* xp1 = x + row_xoff(rg1);

        float xa0[32], xa1[32];
        #pragma unroll
        for (int c = 0; c < 32; c += 4) {
            float4 v0 = *(const float4*)(xp0 + c);
            float4 v1 = *(const float4*)(xp1 + c);
            xa0[c]=v0.x; xa0[c+1]=v0.y; xa0[c+2]=v0.z; xa0[c+3]=v0.w;
            xa1[c]=v1.x; xa1[c+1]=v1.y; xa1[c+2]=v1.z; xa1[c+3]=v1.w;
        }
        if (!has_b) {
            const float* bq = g_bqk[a_lo];
            #pragma unroll
            for (int m = 0; m < 6; m++) {
                int j = z + 16*m;
                float b = bq[j];
                float acc0 = b, acc1 = b;
                const float* wr = wA + j*33;
                #pragma unroll
                for (int c = 0; c < 32; c++) {
                    float w = wr[c];
                    acc0 = fmaf(w, xa0[c], acc0);
                    acc1 = fmaf(w, xa1[c], acc1);
                }
                qkbuf[lr0*96 + j] = acc0;
                qkbuf[lr1*96 + j] = acc1;
            }
        } else {
            const bool h0 = rg0 >= Bnd, h1 = rg1 >= Bnd;
            const float* w0b = h0 ? wB : wA;
            const float* w1b = h1 ? wB : wA;
            const float* bq0 = g_bqk[h0 ? a_hi : a_lo];
            const float* bq1 = g_bqk[h1 ? a_hi : a_lo];
            #pragma unroll
            for (int m = 0; m < 6; m++) {
                int j = z + 16*m;
                float acc0 = bq0[j], acc1 = bq1[j];
                const float* w0 = w0b + j*33;
                const float* w1 = w1b + j*33;
                #pragma unroll
                for (int c = 0; c < 32; c++) {
                    acc0 = fmaf(w0[c], xa0[c], acc0);
                    acc1 = fmaf(w1[c], xa1[c], acc1);
                }
                qkbuf[lr0*96 + j] = acc0;
                qkbuf[lr1*96 + j] = acc1;
            }
        }
    }
    __syncthreads();

    // ================= stage 2: scores + softmax (per group) ===============
    if (z < 10) {
        int h = z / 5, i = z % 5;
        #pragma unroll
        for (int pick = 0; pick < 2; pick++) {
            int g = t0 + pick*16;
            const float* gb = qkbuf + g*5*96;
            float s[5]; float mx = -1e30f;
            #pragma unroll
            for (int j = 0; j < 5; j++) {
                float acc = 0.f;
                const float* qp = gb + i*96 + h*24;
                const float* kp = gb + j*96 + 48 + h*24;
                #pragma unroll
                for (int d = 0; d < 24; d++) acc = fmaf(qp[d], kp[d], acc);
                s[j] = acc * 0.20412414523193154f;   // 1/sqrt(24)
                mx = fmaxf(mx, s[j]);
            }
            float sum = 0.f;
            #pragma unroll
            for (int j = 0; j < 5; j++) { s[j] = __expf(s[j]-mx); sum += s[j]; }
            float inv = 1.f / sum;
            #pragma unroll
            for (int j = 0; j < 5; j++) pbuf[g*50 + z*5 + j] = s[j]*inv;
        }
    }
    __syncthreads();

    // ================= stage 3: vo = x_slice @ Wvo[a]^T + bvo (reuse qkbuf)
    for (int i = tid; i < 96*32; i += THREADS) {
        int j = i >> 5, c = i & 31;
        wA[j*33 + c] = g_Wvo[a_lo][j][c];
        if (has_b) wB[j*33 + c] = g_Wvo[a_hi][j][c];
    }
    __syncthreads();

    for (int ch = 0; ch < 5; ch++) {
        const int lr0 = ch*32 + t0;
        const int lr1 = lr0 + 16;
        const int rg0 = r0 + lr0, rg1 = r0 + lr1;
        const float* xp0 = x + row_xoff(rg0);
        const float* xp1 = x + row_xoff(rg1);

        float xa0[32], xa1[32];
        #pragma unroll
        for (int c = 0; c < 32; c += 4) {
            float4 v0 = *(const float4*)(xp0 + c);
            float4 v1 = *(const float4*)(xp1 + c);
            xa0[c]=v0.x; xa0[c+1]=v0.y; xa0[c+2]=v0.z; xa0[c+3]=v0.w;
            xa1[c]=v1.x; xa1[c+1]=v1.y; xa1[c+2]=v1.z; xa1[c+3]=v1.w;
        }
        if (!has_b) {
            const float* bq = g_bvo[a_lo];
            #pragma unroll
            for (int m = 0; m < 6; m++) {
                int j = z + 16*m;
                float b = bq[j];
                float acc0 = b, acc1 = b;
                const float* wr = wA + j*33;
                #pragma unroll
                for (int c = 0; c < 32; c++) {
                    float w = wr[c];
                    acc0 = fmaf(w, xa0[c], acc0);
                    acc1 = fmaf(w, xa1[c], acc1);
                }
                qkbuf[lr0*96 + j] = acc0;
                qkbuf[lr1*96 + j] = acc1;
            }
        } else {
            const bool h0 = rg0 >= Bnd, h1 = rg1 >= Bnd;
            const float* w0b = h0 ? wB : wA;
            const float* w1b = h1 ? wB : wA;
            const float* bq0 = g_bvo[h0 ? a_hi : a_lo];
            const float* bq1 = g_bvo[h1 ? a_hi : a_lo];
            #pragma unroll
            for (int m = 0; m < 6; m++) {
                int j = z + 16*m;
                float acc0 = bq0[j], acc1 = bq1[j];
                const float* w0 = w0b + j*33;
                const float* w1 = w1b + j*33;
                #pragma unroll
                for (int c = 0; c < 32; c++) {
                    acc0 = fmaf(w0[c], xa0[c], acc0);
                    acc1 = fmaf(w1[c], xa1[c], acc1);
                }
                qkbuf[lr0*96 + j] = acc0;
                qkbuf[lr1*96 + j] = acc1;
            }
        }
    }
    __syncthreads();

    // ===== stage 4: out[m0+g, i*48+e] = out_b[e] + sum_{h,j} p * vo ========
    #pragma unroll
    for (int m = 0; m < 15; m++) {
        int col = z + 16*m;
        int i = col / 48, e = col % 48;
        float ob = out_b[e];
        float acc0 = ob, acc1 = ob;
        int g0 = t0, g1 = t0 + 16;
        #pragma unroll
        for (int h = 0; h < 2; h++) {
            #pragma unroll
            for (int j = 0; j < 5; j++) {
                float p0 = pbuf[g0*50 + (h*5+i)*5 + j];
                float p1 = pbuf[g1*50 + (h*5+i)*5 + j];
                float v0 = qkbuf[(g0*5+j)*96 + h*48 + e];
                float v1 = qkbuf[(g1*5+j)*96 + h*48 + e];
                acc0 = fmaf(p0, v0, acc0);
                acc1 = fmaf(p1, v1, acc1);
            }
        }
        out[(long)(m0+g0)*512 + col] = acc0;
        out[(long)(m0+g1)*512 + col] = acc1;
    }

    // ===== stage 5: extra = x[token, 160:256] @ extra_w^T + extra_b ========
    const float* x0e = x + (long)(m0 + t0)      * 256;
    const float* x1e = x + (long)(m0 + t0 + 16) * 256;
    float* wbuf = wA;   // 48*97 <= 2*96*33 region

    for (int u0 = 0; u0 < 272; u0 += 48) {
        int cnt = (272 - u0) < 48 ? (272 - u0) : 48;   // 48,...,48,32
        int nm  = cnt >> 4;                            // 3 or 2
        __syncthreads();
        for (int i = tid; i < cnt*96; i += THREADS) {
            int r = i / 96, c = i % 96;
            wbuf[r*97 + c] = extra_w[(u0 + r)*96 + c];
        }
        __syncthreads();

        float acc0[3], acc1[3];
        #pragma unroll
        for (int m = 0; m < 3; m++) {
            if (m < nm) {
                float b = extra_b[u0 + z + 16*m];
                acc0[m] = b; acc1[m] = b;
            }
        }
        #pragma unroll
        for (int half = 0; half < 2; half++) {
            float xe0[48], xe1[48];
            #pragma unroll
            for (int c = 0; c < 48; c += 4) {
                float4 v0 = *(const float4*)(x0e + 160 + half*48 + c);
                float4 v1 = *(const float4*)(x1e + 160 + half*48 + c);
                xe0[c]=v0.x; xe0[c+1]=v0.y; xe0[c+2]=v0.z; xe0[c+3]=v0.w;
                xe1[c]=v1.x; xe1[c+1]=v1.y; xe1[c+2]=v1.z; xe1[c+3]=v1.w;
            }
            #pragma unroll
            for (int m = 0; m < 3; m++) {
                if (m < nm) {
                    const float* wr = wbuf + (z + 16*m)*97 + half*48;
                    #pragma unroll
                    for (int c = 0; c < 48; c++) {
                        float w = wr[c];
                        acc0[m] = fmaf(w, xe0[c], acc0[m]);
                        acc1[m] = fmaf(w, xe1[c], acc1[m]);
                    }
                }
            }
        }
        #pragma unroll
        for (int m = 0; m < 3; m++) {
            if (m < nm) {
                int u = u0 + z + 16*m;
                out[(long)(m0+t0)    *512 + 240 + u] = acc0[m];
                out[(long)(m0+t0+16) *512 + 240 + u] = acc1[m];
            }
        }
    }
}

extern "C" void kernel_launch(void* const* d_in, const int* in_sizes, int n_in,
                              void* d_out, int out_size)
{
    // Defensive: map inputs by element count (all distinct).
    const float *x=0, *agg_W=0, *agg_b=0, *ipw=0, *ipb=0, *out_w=0, *out_b=0, *extra_w=0, *extra_b=0;
    for (int i = 0; i < n_in; i++) {
        switch (in_sizes[i]) {
            case 32*4096*256: x       = (const float*)d_in[i]; break;
            case 5*48*32:     agg_W   = (const float*)d_in[i]; break;
            case 5*48:        agg_b   = (const float*)d_in[i]; break;
            case 144*48:      ipw     = (const float*)d_in[i]; break;
            case 144:         ipb     = (const float*)d_in[i]; break;
            case 48*48:       out_w   = (const float*)d_in[i]; break;
            case 48:          out_b   = (const float*)d_in[i]; break;
            case 272*96:      extra_w = (const float*)d_in[i]; break;
            case 272:         extra_b = (const float*)d_in[i]; break;
            default: break;
        }
    }
    float* out = (float*)d_out;

    prep_kernel<<<15, THREADS>>>(agg_W, agg_b, ipw, ipb, out_w);

    const int smem_bytes = SM_FLOATS * (int)sizeof(float);   // 93184
    cudaFuncSetAttribute(main_kernel, cudaFuncAttributeMaxDynamicSharedMemorySize, smem_bytes);
    main_kernel<<<NBLOCKS, THREADS, smem_bytes>>>(x, extra_w, extra_b, out_b, out);
}